// round 12
// baseline (speedup 1.0000x reference)
#include <cuda_runtime.h>
#include <math.h>

#define HH 2048
#define WW 2048
#define NF 64
#define MAXD 12
#define NSLOT 8191            // heap-ordered tree, depths 0..12
#define PXW 32                // patch width  (warp x-span)
#define PXH 4                 // patch height (rows per thread)
#define NPX (WW / PXW)        // 64
#define NPY (HH / PXH)        // 512
#define NPATCH (NPX * NPY)    // 32768
#define GRID 768              // co-resident (launch_bounds(256,8) -> 1184 slots)
#define NTHR 256
#define NWARPS (GRID * 8)     // 6144

// Word encoding (per node):
//   bits [11:0]  split coordinate (interior) or 4095 sentinel (leaf)
//   bits [24:12] child base (interior: 2j+1) / self index (leaf: j -> self-loop)
//   bit  [25]    axis (1 = vertical/x split), 0 on leaves
//   bits [31:26] color index (leaf only)
// Fat node: g_tree4[j] = { word(j), word(left), word(right), 0 } -> 2 levels/LDG.128
__device__ int4 g_tree4[NSLOT];
__device__ int4 g_pre[NPATCH];          // per 32x4 patch: {cur, pd, stop word, 0}
__device__ unsigned g_cnt = 0;          // barrier arrivals (reset by last arriver)
__device__ volatile unsigned g_gen;     // barrier generation (monotone across replays)

__device__ __forceinline__ int make_word(int slot, int idx, int x0, int y0,
                                         int w, int h, int depth, const float* sr)
{
    if (depth == MAXD || w < 2 || h < 2)
        return 4095 | (slot << 12) | (idx << 26);            // leaf, self-loop
    int vert = idx & 1;
    int dim  = vert ? w : h;
    int cut  = max(1, (int)floorf((float)dim * sr[idx]));
    int s    = (vert ? x0 : y0) + cut;
    return s | ((2 * slot + 1) << 12) | (vert << 25);
}

// ---------------------------------------------------------------------------
// Single fused kernel: phase 1 (tree build + patch prefixes, role by block),
// device grid barrier, phase 2 (render, warp-job loop).
// ---------------------------------------------------------------------------
__global__ void __launch_bounds__(NTHR, 8) k_all(
    const float* __restrict__ colors,
    const float* __restrict__ sel,
    const float* __restrict__ ratios,
    float* __restrict__ out)
{
    __shared__ float  s_ratio[NF];
    __shared__ int    s_left[NF], s_right[NF];
    __shared__ float4 s_col[NF];

    const int tid = threadIdx.x;
    const int b   = blockIdx.x;

    // ======================= PHASE 1 =======================
    if (b < 160) {
        {   // argmax: row = tid>>1 (0..127), sub = tid&1 covers 32 elems.
            // First-max tie-break (strict >, lower index wins).
            const int row   = tid >> 1;
            const int sub   = tid & 1;
            const int frame = row >> 1;
            const int side  = row & 1;
            const float4* p = (const float4*)(sel + frame * 2 * NF + side * NF + sub * 32);

            float best = -3.4e38f; int bi = sub * 32;
            #pragma unroll
            for (int v4 = 0; v4 < 8; v4++) {
                float4 q = p[v4];
                float vv[4] = {q.x, q.y, q.z, q.w};
                #pragma unroll
                for (int e = 0; e < 4; e++) {
                    int ii = sub * 32 + v4 * 4 + e;
                    if (vv[e] > best) { best = vv[e]; bi = ii; }
                }
            }
            float ov = __shfl_xor_sync(0xffffffffu, best, 1);
            int   oi = __shfl_xor_sync(0xffffffffu, bi,   1);
            if (ov > best || (ov == best && oi < bi)) { best = ov; bi = oi; }
            if (sub == 0) { if (side == 0) s_left[frame] = bi; else s_right[frame] = bi; }
        }
        if (tid < NF) s_ratio[tid] = ratios[tid];
        __syncthreads();

        if (b < 32) {
            // ---- tree build: thread j walks root -> slot j (branchless) ----
            const int j = b * NTHR + tid;
            if (j < NSLOT) {
                const int depth = 31 - __clz(j + 1);    // 0..12
                int idx = 0, x0 = 0, y0 = 0, w = WW, h = HH;
                bool dead = false;

                for (int k = depth - 1; k >= 0; k--) {
                    bool leaf = (w < 2) | (h < 2);
                    dead = dead | leaf;
                    int  bit  = ((j + 1) >> k) & 1;
                    int  vert = idx & 1;
                    float rt  = s_ratio[idx];
                    int  dim  = vert ? w : h;
                    int  cut  = max(1, (int)floorf((float)dim * rt));
                    int  ndim = bit ? dim - cut : cut;
                    int  oadd = bit ? cut : 0;
                    int  nidx = bit ? s_right[idx] : s_left[idx];
                    if (!dead) {
                        if (vert) { x0 += oadd; w = ndim; }
                        else      { y0 += oadd; h = ndim; }
                        idx = nidx;
                    }
                }
                if (!dead) {
                    const bool jleaf = (depth == MAXD) || (w < 2) || (h < 2);
                    int wj, wl, wr;
                    if (jleaf) {
                        wj = 4095 | (j << 12) | (idx << 26);
                        wl = wj; wr = wj;               // self-loop
                    } else {
                        int vert = idx & 1;
                        int dim  = vert ? w : h;
                        int cut  = max(1, (int)floorf((float)dim * s_ratio[idx]));
                        int s    = (vert ? x0 : y0) + cut;
                        wj = s | ((2 * j + 1) << 12) | (vert << 25);
                        int li = s_left[idx], ri = s_right[idx];
                        if (vert) {
                            wl = make_word(2*j+1, li, x0,     y0, cut,   h, depth+1, s_ratio);
                            wr = make_word(2*j+2, ri, x0+cut, y0, w-cut, h, depth+1, s_ratio);
                        } else {
                            wl = make_word(2*j+1, li, x0, y0,     w, cut,   depth+1, s_ratio);
                            wr = make_word(2*j+2, ri, x0, y0+cut, w, h-cut, depth+1, s_ratio);
                        }
                    }
                    g_tree4[j] = make_int4(wj, wl, wr, 0);
                }
            }
        } else {
            // ---- patch prefix (tree-free, register walk) ----
            const int pid = (b - 32) * NTHR + tid;      // 0..32767
            const int px0 = (pid & (NPX - 1)) * PXW;
            const int py0 = (pid >> 6) * PXH;

            int idx = 0, x0 = 0, y0 = 0, w = WW, h = HH, cur = 0, pd = 0;
            int word;
            while (true) {
                if (pd == MAXD || w < 2 || h < 2) {     // patch inside a leaf
                    word = 4095 | (cur << 12) | (idx << 26);
                    break;
                }
                int vert = idx & 1;
                int dim  = vert ? w : h;
                int cut  = max(1, (int)floorf((float)dim * s_ratio[idx]));
                int s    = (vert ? x0 : y0) + cut;
                int lo   = vert ? px0 : py0;
                int hi   = lo + (vert ? PXW : PXH);
                if (hi <= s) {
                    if (vert) w = cut; else h = cut;
                    idx = s_left[idx];  cur = 2 * cur + 1; pd++;
                } else if (lo >= s) {
                    if (vert) { x0 += cut; w -= cut; } else { y0 += cut; h -= cut; }
                    idx = s_right[idx]; cur = 2 * cur + 2; pd++;
                } else {                                 // split crosses patch
                    word = s | ((2 * cur + 1) << 12) | (vert << 25);
                    break;
                }
            }
            g_pre[pid] = make_int4(cur, pd, word, 0);
        }
        __threadfence();                                 // publish before arriving
    }

    // ======================= GRID BARRIER =======================
    __syncthreads();
    if (tid == 0) {
        unsigned gen0 = g_gen;                           // read BEFORE arriving
        unsigned old  = atomicAdd(&g_cnt, 1);
        if (old == GRID - 1) {
            atomicExch(&g_cnt, 0);                       // reset for next launch
            __threadfence();
            atomicAdd((unsigned*)&g_gen, 1);             // release
        } else {
            while (g_gen == gen0) { __nanosleep(64); }   // spin on generation
        }
    }
    __syncthreads();
    __threadfence();

    // ======================= PHASE 2: RENDER =======================
    if (tid < NF)
        s_col[tid] = make_float4(colors[3 * tid], colors[3 * tid + 1],
                                 colors[3 * tid + 2], 0.f);
    __syncthreads();

    const int lane  = tid & 31;
    const int wglob = b * 8 + (tid >> 5);

    for (int pid = wglob; pid < NPATCH; pid += NWARPS) {
        const int px   = pid & (NPX - 1);
        const int py   = pid >> 6;
        const int wy0  = py * PXH;
        const int x    = px * PXW + lane;
        const int base = wy0 * WW + x;

        const int4 pre  = __ldg(&g_pre[pid]);            // warp-uniform broadcast
        const int  cur0 = pre.x, pd = pre.y, word = pre.z;

        if ((word & 0xFFF) == 4095) {                    // patch inside one leaf
            float4 c = s_col[(unsigned)word >> 26];
            #pragma unroll
            for (int q = 0; q < PXH; q++) {
                out[base + q * WW]               = c.x;
                out[HH * WW + base + q * WW]     = c.y;
                out[2 * HH * WW + base + q * WW] = c.z;
            }
            continue;
        }

        const int TRP = (MAXD - pd + 2) >> 1;            // pair iterations

        float4 col = make_float4(0.f, 0.f, 0.f, 0.f);
        int reachy = -1;

        #pragma unroll
        for (int q = 0; q < PXH; q++) {
            const int y = wy0 + q;
            if (y >= reachy) {                           // warp-convergent trigger
                int c2 = cur0, ry = HH, vb = 0;
                for (int i = 0; i < TRP; i++) {          // branchless, 2 levels/load
                    int4 nd = __ldg(&g_tree4[c2]);
                    int  va = nd.x;
                    int  sA = va & 0xFFF;
                    bool vA = (va & (1 << 25)) != 0;
                    bool gA = (vA ? x : y) >= sA;
                    if (!gA && !vA) ry = min(ry, sA);
                    vb = gA ? nd.z : nd.y;
                    int  sB = vb & 0xFFF;
                    bool vB = (vb & (1 << 25)) != 0;
                    bool gB = (vB ? x : y) >= sB;
                    if (!gB && !vB) ry = min(ry, sB);
                    c2 = ((vb >> 12) & 0x1FFF) + (gB ? 1 : 0);
                }
                col = s_col[(unsigned)vb >> 26];
                reachy = ry;
            }
            out[base + q * WW]               = col.x;
            out[HH * WW + base + q * WW]     = col.y;
            out[2 * HH * WW + base + q * WW] = col.z;
        }
    }
}

extern "C" void kernel_launch(void* const* d_in, const int* in_sizes, int n_in,
                              void* d_out, int out_size) {
    const float* colors = (const float*)d_in[0];   // frame_colors    [64, 3]
    const float* sel    = (const float*)d_in[1];   // frame_selection [64, 2, 64]
    const float* ratios = (const float*)d_in[2];   // split_ratios    [64]
    float* out = (float*)d_out;                    // [3, 2048, 2048] fp32

    k_all<<<GRID, NTHR>>>(colors, sel, ratios, out);
}

// round 13
// speedup vs baseline: 1.1946x; 1.1946x over previous
#include <cuda_runtime.h>
#include <math.h>

#define HH 2048
#define WW 2048
#define NF 64
#define MAXD 12
#define NSLOT 8191            // heap-ordered tree, depths 0..12
#define PXW 32                // patch width  (warp x-span)
#define PXH 4                 // patch height (rows per thread)
#define NPX (WW / PXW)        // 64
#define NPY (HH / PXH)        // 512
#define NPATCH (NPX * NPY)    // 32768

// Word encoding (per node):
//   bits [11:0]  split coordinate (interior) or 4095 sentinel (leaf)
//   bits [24:12] child base (interior: 2j+1) / self index (leaf: j -> self-loop)
//   bit  [25]    axis (1 = vertical/x split), 0 on leaves
//   bits [31:26] color index (leaf only)
// Fat node: g_tree4[j] = { word(j), word(left), word(right), 0 } -> 2 levels/LDG.128
__device__ int4 g_tree4[NSLOT];
__device__ int4 g_pre[NPATCH];      // per 32x4 patch: {cur, pd, stop word, 0}

__device__ __forceinline__ int make_word(int slot, int idx, int x0, int y0,
                                         int w, int h, int depth, const float* sr)
{
    if (depth == MAXD || w < 2 || h < 2)
        return 4095 | (slot << 12) | (idx << 26);            // leaf, self-loop
    int vert = idx & 1;
    int dim  = vert ? w : h;
    int cut  = max(1, (int)floorf((float)dim * sr[idx]));
    int s    = (vert ? x0 : y0) + cut;
    return s | ((2 * slot + 1) << 12) | (vert << 25);
}

// ---------------------------------------------------------------------------
// Kernel 1: fused tree build + patch prefixes (independent roles by block,
// NO synchronization). Blocks 0..31: fat tree (thread j walks root->slot j).
// Blocks 32..159: tree-free per-patch prefix walks. Argmax is recomputed
// per block from registers (cheap, latency-flat).
// ---------------------------------------------------------------------------
__global__ __launch_bounds__(256) void k_build(
    const float* __restrict__ sel,
    const float* __restrict__ ratios)
{
    __shared__ float s_ratio[NF];
    __shared__ int   s_left[NF], s_right[NF];

    const int tid = threadIdx.x;
    const int b   = blockIdx.x;

    {   // argmax: row = tid>>1 (0..127), sub = tid&1 covers 32 elems.
        // First-max tie-break (strict >, lower index wins).
        const int row   = tid >> 1;
        const int sub   = tid & 1;
        const int frame = row >> 1;
        const int side  = row & 1;
        const float4* p = (const float4*)(sel + frame * 2 * NF + side * NF + sub * 32);

        float best = -3.4e38f; int bi = sub * 32;
        #pragma unroll
        for (int v4 = 0; v4 < 8; v4++) {
            float4 q = p[v4];
            float vv[4] = {q.x, q.y, q.z, q.w};
            #pragma unroll
            for (int e = 0; e < 4; e++) {
                int ii = sub * 32 + v4 * 4 + e;
                if (vv[e] > best) { best = vv[e]; bi = ii; }
            }
        }
        float ov = __shfl_xor_sync(0xffffffffu, best, 1);
        int   oi = __shfl_xor_sync(0xffffffffu, bi,   1);
        if (ov > best || (ov == best && oi < bi)) { best = ov; bi = oi; }
        if (sub == 0) { if (side == 0) s_left[frame] = bi; else s_right[frame] = bi; }
    }
    if (tid < NF) s_ratio[tid] = ratios[tid];
    __syncthreads();

    if (b < 32) {
        // ---- fat tree build: thread j walks root -> slot j (branchless) ----
        const int j = b * 256 + tid;
        if (j >= NSLOT) return;

        const int depth = 31 - __clz(j + 1);    // 0..12
        int idx = 0, x0 = 0, y0 = 0, w = WW, h = HH;
        bool dead = false;

        for (int k = depth - 1; k >= 0; k--) {
            bool leaf = (w < 2) | (h < 2);
            dead = dead | leaf;
            int  bit  = ((j + 1) >> k) & 1;
            int  vert = idx & 1;
            float rt  = s_ratio[idx];
            int  dim  = vert ? w : h;
            int  cut  = max(1, (int)floorf((float)dim * rt));
            int  ndim = bit ? dim - cut : cut;
            int  oadd = bit ? cut : 0;
            int  nidx = bit ? s_right[idx] : s_left[idx];
            if (!dead) {
                if (vert) { x0 += oadd; w = ndim; }
                else      { y0 += oadd; h = ndim; }
                idx = nidx;
            }
        }
        if (dead) return;                       // unreachable slot, never read

        const bool jleaf = (depth == MAXD) || (w < 2) || (h < 2);
        int wj, wl, wr;
        if (jleaf) {
            wj = 4095 | (j << 12) | (idx << 26);
            wl = wj; wr = wj;                   // self-loop
        } else {
            int vert = idx & 1;
            int dim  = vert ? w : h;
            int cut  = max(1, (int)floorf((float)dim * s_ratio[idx]));
            int s    = (vert ? x0 : y0) + cut;
            wj = s | ((2 * j + 1) << 12) | (vert << 25);
            int li = s_left[idx], ri = s_right[idx];
            if (vert) {
                wl = make_word(2*j+1, li, x0,     y0, cut,   h, depth+1, s_ratio);
                wr = make_word(2*j+2, ri, x0+cut, y0, w-cut, h, depth+1, s_ratio);
            } else {
                wl = make_word(2*j+1, li, x0, y0,     w, cut,   depth+1, s_ratio);
                wr = make_word(2*j+2, ri, x0, y0+cut, w, h-cut, depth+1, s_ratio);
            }
        }
        g_tree4[j] = make_int4(wj, wl, wr, 0);
    } else {
        // ---- patch prefix (tree-free register walk) ----
        const int pid = (b - 32) * 256 + tid;   // 0..32767
        const int px0 = (pid & (NPX - 1)) * PXW;
        const int py0 = (pid >> 6) * PXH;

        int idx = 0, x0 = 0, y0 = 0, w = WW, h = HH, cur = 0, pd = 0;
        int word;
        while (true) {
            if (pd == MAXD || w < 2 || h < 2) {  // patch inside a leaf
                word = 4095 | (cur << 12) | (idx << 26);
                break;
            }
            int vert = idx & 1;
            int dim  = vert ? w : h;
            int cut  = max(1, (int)floorf((float)dim * s_ratio[idx]));
            int s    = (vert ? x0 : y0) + cut;
            int lo   = vert ? px0 : py0;
            int hi   = lo + (vert ? PXW : PXH);
            if (hi <= s) {
                if (vert) w = cut; else h = cut;
                idx = s_left[idx];  cur = 2 * cur + 1; pd++;
            } else if (lo >= s) {
                if (vert) { x0 += cut; w -= cut; } else { y0 += cut; h -= cut; }
                idx = s_right[idx]; cur = 2 * cur + 2; pd++;
            } else {                             // split crosses patch
                word = s | ((2 * cur + 1) << 12) | (vert << 25);
                break;
            }
        }
        g_pre[pid] = make_int4(cur, pd, word, 0);
    }
}

// ---------------------------------------------------------------------------
// Kernel 2: render. Warp = 32x4 patch, thread = 1 column x 4 rows. One
// broadcast g_pre load; fast path when the patch sits in one leaf; else a
// short branchless descent (2 levels per LDG.128) with row reuse (reachy).
// ---------------------------------------------------------------------------
__global__ __launch_bounds__(256) void k_render(
    const float* __restrict__ colors,
    float* __restrict__ out)
{
    __shared__ float4 s_col[NF];
    const int t = threadIdx.y * 32 + threadIdx.x;
    if (t < NF)
        s_col[t] = make_float4(colors[3 * t], colors[3 * t + 1], colors[3 * t + 2], 0.f);
    __syncthreads();

    const int px   = blockIdx.x;                        // 0..63
    const int py   = blockIdx.y * 8 + threadIdx.y;      // 0..511
    const int wy0  = py * PXH;
    const int x    = px * PXW + threadIdx.x;
    const int base = wy0 * WW + x;

    const int4 pre = __ldg(&g_pre[py * NPX + px]);      // warp-uniform broadcast
    const int cur0 = pre.x, pd = pre.y, word = pre.z;

    if ((word & 0xFFF) == 4095) {                       // patch inside one leaf
        float4 c = s_col[(unsigned)word >> 26];
        #pragma unroll
        for (int q = 0; q < PXH; q++) {
            out[base + q * WW]               = c.x;
            out[HH * WW + base + q * WW]     = c.y;
            out[2 * HH * WW + base + q * WW] = c.z;
        }
        return;
    }

    const int TRP = (MAXD - pd + 2) >> 1;               // pair iterations

    float4 col = make_float4(0.f, 0.f, 0.f, 0.f);
    int reachy = -1;

    #pragma unroll
    for (int q = 0; q < PXH; q++) {
        const int y = wy0 + q;
        if (y >= reachy) {                              // warp-convergent trigger
            int c2 = cur0, ry = HH, vb = 0;
            for (int i = 0; i < TRP; i++) {             // branchless, 2 levels/load
                int4 nd = __ldg(&g_tree4[c2]);
                int  va = nd.x;
                int  sA = va & 0xFFF;
                bool vA = (va & (1 << 25)) != 0;
                bool gA = (vA ? x : y) >= sA;
                if (!gA && !vA) ry = min(ry, sA);
                vb = gA ? nd.z : nd.y;
                int  sB = vb & 0xFFF;
                bool vB = (vb & (1 << 25)) != 0;
                bool gB = (vB ? x : y) >= sB;
                if (!gB && !vB) ry = min(ry, sB);
                c2 = ((vb >> 12) & 0x1FFF) + (gB ? 1 : 0);
            }
            col = s_col[(unsigned)vb >> 26];
            reachy = ry;
        }
        out[base + q * WW]               = col.x;
        out[HH * WW + base + q * WW]     = col.y;
        out[2 * HH * WW + base + q * WW] = col.z;
    }
}

extern "C" void kernel_launch(void* const* d_in, const int* in_sizes, int n_in,
                              void* d_out, int out_size) {
    const float* colors = (const float*)d_in[0];   // frame_colors    [64, 3]
    const float* sel    = (const float*)d_in[1];   // frame_selection [64, 2, 64]
    const float* ratios = (const float*)d_in[2];   // split_ratios    [64]
    float* out = (float*)d_out;                    // [3, 2048, 2048] fp32

    k_build<<<160, 256>>>(sel, ratios);            // blocks 0-31: tree; 32-159: prefixes

    dim3 block(32, 8);
    dim3 grid(NPX, NPY / 8);                       // 64 x 64
    k_render<<<grid, block>>>(colors, out);
}